// round 2
// baseline (speedup 1.0000x reference)
#include <cuda_runtime.h>
#include <cuda_bf16.h>
#include <math.h>

// loss_soft_add, fully fused single kernel:
// per row of 25 floats, 6 chunks of 4 -> 3*softmax(chunk),
// L1 diff vs tar over first 24 cols, mean over 24, summed over all rows.
// Output: single float scalar.
//
// Cross-block reduction via threadfence pattern with a self-resetting
// atomicInc counter (wraps to 0 at gridDim.x), so the kernel is
// replay-deterministic inside a CUDA graph with zero auxiliary launches.

#define ROWS_PER_TILE 256
#define ROW_LEN       25
#define FLOATS_PER_TILE (ROWS_PER_TILE * ROW_LEN)   // 6400
#define VEC4_PER_TILE   (FLOATS_PER_TILE / 4)       // 1600
#define MAX_GRID 1024

__device__ double g_partials[MAX_GRID];
__device__ unsigned int g_count = 0;   // always returns to 0 each launch (atomicInc wrap)

__device__ __forceinline__ float row_loss6(const float* __restrict__ prow,
                                           const float* __restrict__ trow)
{
    float s = 0.0f;
    #pragma unroll
    for (int j = 0; j < 6; j++) {
        float a = prow[4 * j + 0];
        float b = prow[4 * j + 1];
        float c = prow[4 * j + 2];
        float d = prow[4 * j + 3];
        float m = fmaxf(fmaxf(a, b), fmaxf(c, d));
        float ea = __expf(a - m);
        float eb = __expf(b - m);
        float ec = __expf(c - m);
        float ed = __expf(d - m);
        float inv = 3.0f / (ea + eb + ec + ed);
        s += fabsf(ea * inv - trow[4 * j + 0]);
        s += fabsf(eb * inv - trow[4 * j + 1]);
        s += fabsf(ec * inv - trow[4 * j + 2]);
        s += fabsf(ed * inv - trow[4 * j + 3]);
    }
    return s;
}

__global__ __launch_bounds__(ROWS_PER_TILE, 4)
void loss_kernel(const float* __restrict__ pre,
                 const float* __restrict__ tar,
                 long long nrows,
                 float* __restrict__ out)
{
    __shared__ float spre[FLOATS_PER_TILE];
    __shared__ float star[FLOATS_PER_TILE];
    __shared__ double red[ROWS_PER_TILE];
    __shared__ bool isLast;

    const int tid = threadIdx.x;
    const long long ntiles = nrows / ROWS_PER_TILE;

    float acc = 0.0f;

    for (long long tile = blockIdx.x; tile < ntiles; tile += gridDim.x) {
        const long long base = tile * (long long)FLOATS_PER_TILE;

        // ---- stage PRE and TAR tiles together (coalesced float4, 2x MLP) ----
        {
            const float4* p4 = reinterpret_cast<const float4*>(pre + base);
            const float4* t4 = reinterpret_cast<const float4*>(tar + base);
            float4* sp = reinterpret_cast<float4*>(spre);
            float4* st = reinterpret_cast<float4*>(star);
            #pragma unroll
            for (int i = tid; i < VEC4_PER_TILE; i += ROWS_PER_TILE) {
                sp[i] = p4[i];
                st[i] = t4[i];
            }
        }
        __syncthreads();

        // ---- fused softmax + L1 diff, one row per thread ----
        acc += row_loss6(spre + tid * ROW_LEN, star + tid * ROW_LEN);
        __syncthreads();   // before next tile overwrites smem
    }

    // ---- tail rows (nrows not multiple of 256), handled by block 0 ----
    {
        const long long done = ntiles * (long long)ROWS_PER_TILE;
        const long long rem = nrows - done;
        if (blockIdx.x == 0 && (long long)tid < rem) {
            acc += row_loss6(pre + (done + tid) * (long long)ROW_LEN,
                             tar + (done + tid) * (long long)ROW_LEN);
        }
    }

    // ---- block tree reduction (deterministic) ----
    red[tid] = (double)acc;
    __syncthreads();
    #pragma unroll
    for (int s = ROWS_PER_TILE / 2; s > 0; s >>= 1) {
        if (tid < s) red[tid] += red[tid + s];
        __syncthreads();
    }

    // ---- cross-block: threadfence reduction, self-resetting counter ----
    if (tid == 0) {
        g_partials[blockIdx.x] = red[0];
        __threadfence();
        // wraps to 0 when old == gridDim.x-1 -> counter is 0 again for next replay
        unsigned int old = atomicInc(&g_count, gridDim.x - 1);
        isLast = (old == gridDim.x - 1);
    }
    __syncthreads();

    if (isLast) {
        __threadfence();  // make all blocks' partials visible
        double s = 0.0;
        for (int i = tid; i < (int)gridDim.x; i += ROWS_PER_TILE)
            s += g_partials[i];
        red[tid] = s;
        __syncthreads();
        #pragma unroll
        for (int st = ROWS_PER_TILE / 2; st > 0; st >>= 1) {
            if (tid < st) red[tid] += red[tid + st];
            __syncthreads();
        }
        if (tid == 0)
            out[0] = (float)(red[0] * (1.0 / 24.0));
    }
}

extern "C" void kernel_launch(void* const* d_in, const int* in_sizes, int n_in,
                              void* d_out, int out_size)
{
    const float* pre = (const float*)d_in[0];
    const float* tar = (const float*)d_in[1];
    long long nrows = (long long)in_sizes[0] / ROW_LEN;
    long long ntiles = nrows / ROWS_PER_TILE;

    // 148 SMs x 4 resident blocks (52KB smem, launch_bounds) = 592
    long long g = ntiles > 0 ? ntiles : 1;
    int grid = (int)(g < 592 ? g : 592);

    loss_kernel<<<grid, ROWS_PER_TILE>>>(pre, tar, nrows, (float*)d_out);
}

// round 3
// speedup vs baseline: 1.3107x; 1.3107x over previous
#include <cuda_runtime.h>
#include <cuda_bf16.h>
#include <math.h>

// loss_soft_add, single fused kernel:
// per row of 25 floats, 6 chunks of 4 -> 3*softmax(chunk),
// L1 diff vs tar over first 24 cols, mean over 24, summed over all rows.
// Output: single float scalar.
//
// Structure = R1's high-throughput body (single smem tile reused for pre
// then tar; out24 kept in registers between phases -> 26KB smem, 8 blocks/SM)
// + fused cross-block finish (threadfence + self-resetting atomicInc), so
// there are no auxiliary launches and the kernel is graph-replay safe.

#define ROWS_PER_TILE 256
#define ROW_LEN       25
#define FLOATS_PER_TILE (ROWS_PER_TILE * ROW_LEN)   // 6400
#define VEC4_PER_TILE   (FLOATS_PER_TILE / 4)       // 1600
#define MAX_GRID 1184

__device__ double g_partials[MAX_GRID];
__device__ unsigned int g_count = 0;   // wraps back to 0 every launch

__global__ __launch_bounds__(ROWS_PER_TILE)
void loss_kernel(const float* __restrict__ pre,
                 const float* __restrict__ tar,
                 long long nrows,
                 float* __restrict__ out)
{
    __shared__ float sbuf[FLOATS_PER_TILE];
    __shared__ float warp_red[8];
    __shared__ bool isLast;

    const int tid  = threadIdx.x;
    const int lane = tid & 31;
    const int wid  = tid >> 5;
    const long long ntiles = nrows / ROWS_PER_TILE;

    float acc = 0.0f;

    for (long long tile = blockIdx.x; tile < ntiles; tile += gridDim.x) {
        const long long base = tile * (long long)FLOATS_PER_TILE;

        // ---- stage PRE tile (coalesced float4) ----
        {
            const float4* p4 = reinterpret_cast<const float4*>(pre + base);
            float4* s4 = reinterpret_cast<float4*>(sbuf);
            #pragma unroll
            for (int i = tid; i < VEC4_PER_TILE; i += ROWS_PER_TILE)
                s4[i] = p4[i];
        }
        __syncthreads();

        // ---- 3*softmax per 4-chunk; out24 stays in registers ----
        float o[24];
        {
            const float* row = sbuf + tid * ROW_LEN;  // stride 25: conflict-free
            #pragma unroll
            for (int j = 0; j < 6; j++) {
                float a = row[4 * j + 0];
                float b = row[4 * j + 1];
                float c = row[4 * j + 2];
                float d = row[4 * j + 3];
                float m = fmaxf(fmaxf(a, b), fmaxf(c, d));
                float ea = __expf(a - m);
                float eb = __expf(b - m);
                float ec = __expf(c - m);
                float ed = __expf(d - m);
                float inv = 3.0f / (ea + eb + ec + ed);
                o[4 * j + 0] = ea * inv;
                o[4 * j + 1] = eb * inv;
                o[4 * j + 2] = ec * inv;
                o[4 * j + 3] = ed * inv;
            }
        }
        __syncthreads();

        // ---- stage TAR tile into same buffer ----
        {
            const float4* t4 = reinterpret_cast<const float4*>(tar + base);
            float4* s4 = reinterpret_cast<float4*>(sbuf);
            #pragma unroll
            for (int i = tid; i < VEC4_PER_TILE; i += ROWS_PER_TILE)
                s4[i] = t4[i];
        }
        __syncthreads();

        // ---- L1 diff over 24 elems ----
        {
            const float* row = sbuf + tid * ROW_LEN;
            float s = 0.0f;
            #pragma unroll
            for (int k = 0; k < 24; k++)
                s += fabsf(o[k] - row[k]);
            acc += s;
        }
        __syncthreads();  // before next tile overwrites sbuf
    }

    // ---- tail rows (nrows % 256), block 0 only ----
    {
        const long long done = ntiles * (long long)ROWS_PER_TILE;
        const long long rem = nrows - done;
        if (blockIdx.x == 0 && (long long)tid < rem) {
            const float* prow = pre + (done + tid) * (long long)ROW_LEN;
            const float* trow = tar + (done + tid) * (long long)ROW_LEN;
            float s = 0.0f;
            #pragma unroll
            for (int j = 0; j < 6; j++) {
                float a = prow[4 * j + 0];
                float b = prow[4 * j + 1];
                float c = prow[4 * j + 2];
                float d = prow[4 * j + 3];
                float m = fmaxf(fmaxf(a, b), fmaxf(c, d));
                float ea = __expf(a - m);
                float eb = __expf(b - m);
                float ec = __expf(c - m);
                float ed = __expf(d - m);
                float inv = 3.0f / (ea + eb + ec + ed);
                s += fabsf(ea * inv - trow[4 * j + 0]);
                s += fabsf(eb * inv - trow[4 * j + 1]);
                s += fabsf(ec * inv - trow[4 * j + 2]);
                s += fabsf(ed * inv - trow[4 * j + 3]);
            }
            acc += s;
        }
    }

    // ---- block reduction: warp shuffle + 8-entry smem ----
    #pragma unroll
    for (int off = 16; off > 0; off >>= 1)
        acc += __shfl_down_sync(0xFFFFFFFFu, acc, off);
    if (lane == 0) warp_red[wid] = acc;
    __syncthreads();
    if (wid == 0) {
        float v = (lane < 8) ? warp_red[lane] : 0.0f;
        #pragma unroll
        for (int off = 4; off > 0; off >>= 1)
            v += __shfl_down_sync(0xFFFFFFFFu, v, off);

        if (lane == 0) {
            g_partials[blockIdx.x] = (double)v;
            __threadfence();
            unsigned int old = atomicInc(&g_count, gridDim.x - 1);
            isLast = (old == gridDim.x - 1);
        }
    }
    __syncthreads();

    // ---- last block reduces all partials (deterministic order) ----
    if (isLast) {
        __threadfence();
        double s = 0.0;
        for (int i = tid; i < (int)gridDim.x; i += ROWS_PER_TILE)
            s += g_partials[i];
        // double tree via shuffle (64-bit shuffles)
        #pragma unroll
        for (int off = 16; off > 0; off >>= 1)
            s += __shfl_down_sync(0xFFFFFFFFu, s, off);
        __shared__ double dred[8];
        if (lane == 0) dred[wid] = s;
        __syncthreads();
        if (wid == 0) {
            double v = (lane < 8) ? dred[lane] : 0.0;
            #pragma unroll
            for (int off = 4; off > 0; off >>= 1)
                v += __shfl_down_sync(0xFFFFFFFFu, v, off);
            if (lane == 0)
                out[0] = (float)(v * (1.0 / 24.0));
        }
    }
}

extern "C" void kernel_launch(void* const* d_in, const int* in_sizes, int n_in,
                              void* d_out, int out_size)
{
    const float* pre = (const float*)d_in[0];
    const float* tar = (const float*)d_in[1];
    long long nrows = (long long)in_sizes[0] / ROW_LEN;
    long long ntiles = nrows / ROWS_PER_TILE;

    long long g = ntiles > 0 ? ntiles : 1;
    int grid = (int)(g < MAX_GRID ? g : MAX_GRID);

    loss_kernel<<<grid, ROWS_PER_TILE>>>(pre, tar, nrows, (float*)d_out);
}